// round 7
// baseline (speedup 1.0000x reference)
#include <cuda_runtime.h>
#include <cuda_bf16.h>
#include <cstdint>

// ---------------- problem shape ----------------
#define B_    32
#define C_    64
#define HW_   4096
#define K_    512
#define NPIX  131072
#define NE    8388608
#define TPB   256
#define TILE_M 256
#define NTILES (NPIX / TILE_M)   // 512
#define EPS_SCREEN 1e-4f
#define EPAD  72                 // codebook row stride in bf16 (conflict-free frags)
#define ZPAD  65                 // z tile row stride in f32

// ---------------- smem layout (bytes) ----------------
#define SM_E0   0                        // 512 x EPAD bf16 = 73728
#define SM_E1   73728                    // 73728
#define SM_Z    147456                   // 256 x 65 f32 = 66560
#define SM_EN   214016                   // 512 f32 = 2048
#define SM_M1   216064                   // 256 f32
#define SM_K1   217088                   // 256 i32
#define SM_M2   218112                   // 256 f32
#define SM_FL   219136                   // 256 i32
#define SM_FC   220160                   // 4 (+4 pad)
#define SM_RED  220168                   // 256 f32 = 1024
#define SM_TOTAL 221192

__device__ float g_partials[NTILES];
__device__ unsigned int g_count;

// ---------------- helpers ----------------
__device__ __forceinline__ void mma16816(float* c, const uint32_t* a,
                                         uint32_t b0, uint32_t b1) {
    asm volatile(
        "mma.sync.aligned.m16n8k16.row.col.f32.bf16.bf16.f32 "
        "{%0,%1,%2,%3}, {%4,%5,%6,%7}, {%8,%9}, {%0,%1,%2,%3};"
        : "+f"(c[0]), "+f"(c[1]), "+f"(c[2]), "+f"(c[3])
        : "r"(a[0]), "r"(a[1]), "r"(a[2]), "r"(a[3]), "r"(b0), "r"(b1));
}

// split x,y into bf16 main pair + bf16 residual pair (packed lo=x hi=y)
__device__ __forceinline__ void bfsplit2(float x, float y,
                                         uint32_t& mn, uint32_t& rs) {
    __nv_bfloat16 hx = __float2bfloat16(x);
    __nv_bfloat16 hy = __float2bfloat16(y);
    float rx = x - __bfloat162float(hx);
    float ry = y - __bfloat162float(hy);
    __nv_bfloat162 m; m.x = hx; m.y = hy;
    __nv_bfloat162 r; r.x = __float2bfloat16(rx); r.y = __float2bfloat16(ry);
    mn = *(uint32_t*)&m;
    rs = *(uint32_t*)&r;
}

// packed f32x2 (exact fallback path, identical arithmetic to round-1)
__device__ __forceinline__ unsigned long long fma2(unsigned long long a,
                                                   unsigned long long b,
                                                   unsigned long long c) {
    unsigned long long d;
    asm("fma.rn.f32x2 %0, %1, %2, %3;" : "=l"(d) : "l"(a), "l"(b), "l"(c));
    return d;
}
__device__ __forceinline__ unsigned long long add2(unsigned long long a,
                                                   unsigned long long b) {
    unsigned long long d;
    asm("add.rn.f32x2 %0, %1, %2;" : "=l"(d) : "l"(a), "l"(b));
    return d;
}
__device__ __forceinline__ unsigned long long pack2(float x, float y) {
    unsigned long long u;
    asm("mov.b64 %0, {%1, %2};" : "=l"(u) : "f"(x), "f"(y));
    return u;
}
__device__ __forceinline__ float2 unpack2(unsigned long long u) {
    float2 f;
    asm("mov.b64 {%0, %1}, %2;" : "=f"(f.x), "=f"(f.y) : "l"(u));
    return f;
}

// ---------------- kernel ----------------
__global__ void __launch_bounds__(TPB, 1)
vq_mma(const float* __restrict__ z, const float* __restrict__ cb,
       float* __restrict__ zq_out, float* __restrict__ idx_out,
       float* __restrict__ loss_out) {
    extern __shared__ char smem[];
    __nv_bfloat16* e0s = (__nv_bfloat16*)(smem + SM_E0);
    __nv_bfloat16* e1s = (__nv_bfloat16*)(smem + SM_E1);
    float* zsm  = (float*)(smem + SM_Z);
    float* en_s = (float*)(smem + SM_EN);
    float* sm1  = (float*)(smem + SM_M1);
    int*   sk1  = (int*)  (smem + SM_K1);
    float* sm2  = (float*)(smem + SM_M2);
    int*   flst = (int*)  (smem + SM_FL);
    int*   fcnt = (int*)  (smem + SM_FC);
    float* red  = (float*)(smem + SM_RED);

    const int tid  = threadIdx.x;
    const int wid  = tid >> 5;
    const int lane = tid & 31;
    const int q    = lane & 3;        // col-pair / k-pair selector
    const int g    = lane >> 2;       // row / n selector

    if (tid == 0) *fcnt = 0;

    // --- stage codebook: bf16 2-splits + exact ||e||^2 ---
    for (int i = tid; i < K_ * C_; i += TPB) {
        const int n = i >> 6, c = i & 63;
        float e = cb[i];
        __nv_bfloat16 h0 = __float2bfloat16(e);
        float r = e - __bfloat162float(h0);
        e0s[n * EPAD + c] = h0;
        e1s[n * EPAD + c] = __float2bfloat16(r);
    }
    for (int k = tid; k < K_; k += TPB) {
        const float* cp = cb + k * C_;
        float s = 0.f;
        #pragma unroll
        for (int c = 0; c < C_; ++c) s = fmaf(cp[c], cp[c], s);
        en_s[k] = s;
    }

    // --- stage z tile (256 pixels, f32, transposed to [pixel][channel]) ---
    const int tile = blockIdx.x;
    const int bb   = tile >> 4;            // batch (16 tiles per batch)
    const int hwb  = (tile & 15) * TILE_M; // hw base
    const float* zb = z + (size_t)bb * (C_ * HW_);
    for (int i = tid; i < 64 * 64; i += TPB) {
        const int c = i >> 6, j = i & 63;
        float4 v = *(const float4*)(zb + c * HW_ + hwb + j * 4);
        zsm[(j * 4 + 0) * ZPAD + c] = v.x;
        zsm[(j * 4 + 1) * ZPAD + c] = v.y;
        zsm[(j * 4 + 2) * ZPAD + c] = v.z;
        zsm[(j * 4 + 3) * ZPAD + c] = v.w;
    }
    __syncthreads();

    // --- build A fragments in registers: 2 rowfrags x 4 ksteps ---
    // rowfrag rf covers rows wid*32 + rf*16 + {g, g+8}
    uint32_t az0[2][4][4], az1[2][4][4];
    #pragma unroll
    for (int rf = 0; rf < 2; ++rf) {
        const int r0 = wid * 32 + rf * 16 + g;
        const int r1 = r0 + 8;
        #pragma unroll
        for (int ks = 0; ks < 4; ++ks) {
            const int kc = ks * 16 + 2 * q;
            bfsplit2(zsm[r0 * ZPAD + kc],     zsm[r0 * ZPAD + kc + 1], az0[rf][ks][0], az1[rf][ks][0]);
            bfsplit2(zsm[r1 * ZPAD + kc],     zsm[r1 * ZPAD + kc + 1], az0[rf][ks][1], az1[rf][ks][1]);
            bfsplit2(zsm[r0 * ZPAD + kc + 8], zsm[r0 * ZPAD + kc + 9], az0[rf][ks][2], az1[rf][ks][2]);
            bfsplit2(zsm[r1 * ZPAD + kc + 8], zsm[r1 * ZPAD + kc + 9], az0[rf][ks][3], az1[rf][ks][3]);
        }
    }

    // --- scan 512 codes, 8 per iteration; screen mins in registers ---
    // trackers: t = rf*2 + pair; row = wid*32 + rf*16 + pair*8 + g
    float m1v[4] = {3.4e38f, 3.4e38f, 3.4e38f, 3.4e38f};
    float m2v[4] = {3.4e38f, 3.4e38f, 3.4e38f, 3.4e38f};
    int   k1v[4] = {0, 0, 0, 0};

    #pragma unroll 1
    for (int nt = 0; nt < 64; ++nt) {
        const int n = nt * 8 + g;
        const uint32_t* e0r = (const uint32_t*)(e0s + n * EPAD);
        const uint32_t* e1r = (const uint32_t*)(e1s + n * EPAD);
        uint32_t be0[4][2], be1[4][2];
        #pragma unroll
        for (int ks = 0; ks < 4; ++ks) {
            be0[ks][0] = e0r[ks * 8 + q];
            be0[ks][1] = e0r[ks * 8 + q + 4];
            be1[ks][0] = e1r[ks * 8 + q];
            be1[ks][1] = e1r[ks * 8 + q + 4];
        }
        float accA[2][4] = {{0.f,0.f,0.f,0.f},{0.f,0.f,0.f,0.f}};
        float accB[2][4] = {{0.f,0.f,0.f,0.f},{0.f,0.f,0.f,0.f}};
        #pragma unroll
        for (int rf = 0; rf < 2; ++rf) {
            #pragma unroll
            for (int ks = 0; ks < 4; ++ks) {
                mma16816(accA[rf], az0[rf][ks], be0[ks][0], be0[ks][1]);  // z0*e0
                mma16816(accA[rf], az1[rf][ks], be0[ks][0], be0[ks][1]);  // z1*e0
                mma16816(accB[rf], az0[rf][ks], be1[ks][0], be1[ks][1]);  // z0*e1
            }
        }
        const int kc0 = nt * 8 + 2 * q;
        const float en0 = en_s[kc0], en1 = en_s[kc0 + 1];
        #pragma unroll
        for (int rf = 0; rf < 2; ++rf) {
            #pragma unroll
            for (int pr = 0; pr < 2; ++pr) {
                const int t = rf * 2 + pr;
                float s0 = fmaf(-2.f, accA[rf][pr * 2 + 0] + accB[rf][pr * 2 + 0], en0);
                float s1 = fmaf(-2.f, accA[rf][pr * 2 + 1] + accB[rf][pr * 2 + 1], en1);
                if (s0 < m1v[t])      { m2v[t] = m1v[t]; m1v[t] = s0; k1v[t] = kc0; }
                else if (s0 < m2v[t]) { m2v[t] = s0; }
                if (s1 < m1v[t])      { m2v[t] = m1v[t]; m1v[t] = s1; k1v[t] = kc0 + 1; }
                else if (s1 < m2v[t]) { m2v[t] = s1; }
            }
        }
    }

    // --- reduce across the 4 lanes sharing each row (q = 0..3), write row results ---
    #pragma unroll
    for (int t = 0; t < 4; ++t) {
        float m1 = m1v[t], m2 = m2v[t];
        int   k1 = k1v[t];
        #pragma unroll
        for (int off = 1; off <= 2; off <<= 1) {
            float om1 = __shfl_xor_sync(0xFFFFFFFFu, m1, off);
            float om2 = __shfl_xor_sync(0xFFFFFFFFu, m2, off);
            int   ok1 = __shfl_xor_sync(0xFFFFFFFFu, k1, off);
            if (om1 < m1 || (om1 == m1 && ok1 < k1)) {
                m2 = fminf(m1, om2); m1 = om1; k1 = ok1;
            } else {
                m2 = fminf(m2, om1);
            }
        }
        if (q == 0) {
            const int row = wid * 32 + (t >> 1) * 16 + (t & 1) * 8 + g;
            sm1[row] = m1; sk1[row] = k1; sm2[row] = m2;
        }
    }
    __syncthreads();

    // --- decision pass: one thread per pixel ---
    float lsum = 0.f;
    {
        const int m = tid;
        const float m1 = sm1[m], m2 = sm2[m];
        const int kk = sk1[m];
        if (m2 - m1 < EPS_SCREEN) {
            flst[atomicAdd(fcnt, 1)] = m;       // ambiguous -> exact path
        } else {
            const int p  = tile * TILE_M + m;
            const int hw = hwb + m;
            const float4* cr = (const float4*)(cb + kk * C_);
            float* zo = zq_out + (size_t)bb * (C_ * HW_) + hw;
            const float* zs = zsm + m * ZPAD;
            float ls = 0.f;
            #pragma unroll
            for (int j4 = 0; j4 < 16; ++j4) {
                float4 qv = cr[j4];
                const float qa[4] = {qv.x, qv.y, qv.z, qv.w};
                #pragma unroll
                for (int t = 0; t < 4; ++t) {
                    const int c = j4 * 4 + t;
                    float x = zs[c];
                    float d = qa[t] - x;
                    ls = fmaf(d, d, ls);
                    zo[c * HW_] = x + d;
                }
            }
            lsum += ls;
            idx_out[p] = (float)kk;
        }
    }
    __syncthreads();

    // --- exact fallback: one warp per flagged pixel (round-1 arithmetic) ---
    const int F = *fcnt;
    for (int e = wid; e < F; e += 8) {
        const int mm = flst[e];
        const float* zs = zsm + mm * ZPAD;
        float zn = 0.f;
        unsigned long long zr[32];
        #pragma unroll
        for (int i = 0; i < 32; ++i) {
            float x = zs[2 * i], y = zs[2 * i + 1];
            zn = fmaf(x, x, zn); zn = fmaf(y, y, zn);
            zr[i] = pack2(x, y);
        }
        float best = 3.402823466e38f;
        int   bk   = 0;
        #pragma unroll 1
        for (int t = 0; t < 16; ++t) {
            const int k = lane + (t << 5);
            const ulonglong2* cp = (const ulonglong2*)(cb + k * C_);
            unsigned long long a0 = 0ull, a1 = 0ull, a2 = 0ull, a3 = 0ull;
            #pragma unroll
            for (int j = 0; j < 16; j += 2) {
                ulonglong2 v0 = cp[j];
                ulonglong2 v1 = cp[j + 1];
                a0 = fma2(zr[2 * j + 0], v0.x, a0);
                a1 = fma2(zr[2 * j + 1], v0.y, a1);
                a2 = fma2(zr[2 * j + 2], v1.x, a2);
                a3 = fma2(zr[2 * j + 3], v1.y, a3);
            }
            a0 = add2(a0, a1); a2 = add2(a2, a3); a0 = add2(a0, a2);
            float2 f = unpack2(a0);
            float dist = (zn + en_s[k]) - 2.0f * (f.x + f.y);
            if (dist < best) { best = dist; bk = k; }
        }
        #pragma unroll
        for (int off = 16; off > 0; off >>= 1) {
            float ob = __shfl_down_sync(0xFFFFFFFFu, best, off);
            int   ok = __shfl_down_sync(0xFFFFFFFFu, bk, off);
            if (ob < best || (ob == best && ok < bk)) { best = ob; bk = ok; }
        }
        if (lane == 0) {
            const int p  = tile * TILE_M + mm;
            const int hw = hwb + mm;
            const float* cbv = cb + bk * C_;
            float* zo = zq_out + (size_t)bb * (C_ * HW_) + hw;
            float ls = 0.f;
            #pragma unroll
            for (int c = 0; c < C_; ++c) {
                float x = zs[c];
                float d = cbv[c] - x;
                ls = fmaf(d, d, ls);
                zo[c * HW_] = x + d;
            }
            lsum += ls;
            idx_out[p] = (float)bk;
        }
    }

    // --- loss reduction ---
    __syncthreads();
    #pragma unroll
    for (int off = 16; off > 0; off >>= 1)
        lsum += __shfl_down_sync(0xFFFFFFFFu, lsum, off);
    if (lane == 0) red[wid] = lsum;
    __syncthreads();
    if (tid == 0) {
        float t = 0.f;
        #pragma unroll
        for (int w = 0; w < 8; ++w) t += red[w];
        g_partials[blockIdx.x] = t;
        __threadfence();
        unsigned int old = atomicAdd(&g_count, 1u);
        *fcnt = (old == NTILES - 1) ? 1 : 0;
    }
    __syncthreads();
    if (*fcnt) {
        float v0, v1;
        asm volatile("ld.global.cg.f32 %0, [%1];" : "=f"(v0) : "l"(g_partials + tid));
        asm volatile("ld.global.cg.f32 %0, [%1];" : "=f"(v1) : "l"(g_partials + tid + 256));
        red[tid] = v0 + v1;
        __syncthreads();
        for (int off = 128; off > 0; off >>= 1) {
            if (tid < off) red[tid] += red[tid + off];
            __syncthreads();
        }
        if (tid == 0) {
            float qv = red[0] / (float)NE;   // q_loss == e_loss numerically
            loss_out[0] = qv + 0.25f * qv;
            g_count = 0;                     // reset for next graph replay
        }
    }
}

extern "C" void kernel_launch(void* const* d_in, const int* in_sizes, int n_in,
                              void* d_out, int out_size) {
    const float* z  = (const float*)d_in[0];   // z_e [32,64,64,64] f32
    const float* cb = (const float*)d_in[1];   // codebook [512,64] f32
    float* out  = (float*)d_out;
    float* zq   = out;               // [NE]
    float* idx  = out + NE;          // [NPIX]
    float* loss = out + NE + NPIX;   // [1]

    cudaFuncSetAttribute(vq_mma, cudaFuncAttributeMaxDynamicSharedMemorySize, SM_TOTAL);
    vq_mma<<<NTILES, TPB, SM_TOTAL>>>(z, cb, zq, idx, loss);
}

// round 8
// speedup vs baseline: 1.4364x; 1.4364x over previous
#include <cuda_runtime.h>
#include <cuda_bf16.h>
#include <cstdint>

// ---------------- problem shape ----------------
#define B_    32
#define C_    64
#define HW_   4096
#define K_    512
#define NPIX  131072
#define NE    8388608
#define TPB   256
#define TILE_M 256
#define NTILES (NPIX / TILE_M)   // 512
#define GRID_ 148
#define EPS_SCREEN 1e-4f
#define EW    36                 // permuted codebook row stride in u32 words
#define ZPAD  65                 // z tile row stride in f32

// ---------------- smem layout (bytes) ----------------
#define SM_E0   0                        // 512 x 36 u32 = 73728
#define SM_E1   73728                    // 73728
#define SM_Z    147456                   // 256 x 65 f32 = 66560
#define SM_EN   214016                   // 512 f32 = 2048
#define SM_M1   216064                   // 256 f32
#define SM_K1   217088                   // 256 i32
#define SM_M2   218112                   // 256 f32
#define SM_K2   219136                   // 256 i32
#define SM_M3   220160                   // 256 f32
#define SM_FL   221184                   // 256 i32
#define SM_FC   222208                   // 8
#define SM_RED  222216                   // 256 f32
#define SM_TOTAL 223240

__device__ float g_partials[GRID_];
__device__ unsigned int g_count;

// ---------------- helpers ----------------
__device__ __forceinline__ void mma16816(float* c, const uint32_t* a,
                                         uint32_t b0, uint32_t b1) {
    asm volatile(
        "mma.sync.aligned.m16n8k16.row.col.f32.bf16.bf16.f32 "
        "{%0,%1,%2,%3}, {%4,%5,%6,%7}, {%8,%9}, {%0,%1,%2,%3};"
        : "+f"(c[0]), "+f"(c[1]), "+f"(c[2]), "+f"(c[3])
        : "r"(a[0]), "r"(a[1]), "r"(a[2]), "r"(a[3]), "r"(b0), "r"(b1));
}

__device__ __forceinline__ void bfsplit2(float x, float y,
                                         uint32_t& mn, uint32_t& rs) {
    __nv_bfloat16 hx = __float2bfloat16(x);
    __nv_bfloat16 hy = __float2bfloat16(y);
    float rx = x - __bfloat162float(hx);
    float ry = y - __bfloat162float(hy);
    __nv_bfloat162 m; m.x = hx; m.y = hy;
    __nv_bfloat162 r; r.x = __float2bfloat16(rx); r.y = __float2bfloat16(ry);
    mn = *(uint32_t*)&m;
    rs = *(uint32_t*)&r;
}

// packed f32x2 (exact-path arithmetic, identical to round-1)
__device__ __forceinline__ unsigned long long fma2(unsigned long long a,
                                                   unsigned long long b,
                                                   unsigned long long c) {
    unsigned long long d;
    asm("fma.rn.f32x2 %0, %1, %2, %3;" : "=l"(d) : "l"(a), "l"(b), "l"(c));
    return d;
}
__device__ __forceinline__ unsigned long long add2(unsigned long long a,
                                                   unsigned long long b) {
    unsigned long long d;
    asm("add.rn.f32x2 %0, %1, %2;" : "=l"(d) : "l"(a), "l"(b));
    return d;
}
__device__ __forceinline__ unsigned long long pack2(float x, float y) {
    unsigned long long u;
    asm("mov.b64 %0, {%1, %2};" : "=l"(u) : "f"(x), "f"(y));
    return u;
}
__device__ __forceinline__ float2 unpack2(unsigned long long u) {
    float2 f;
    asm("mov.b64 {%0, %1}, %2;" : "=f"(f.x), "=f"(f.y) : "l"(u));
    return f;
}

// exact dist for one code, bit-identical to round-1 chain (zs = 64 f32 from smem)
__device__ __forceinline__ float exact_dist_k(const float* zs, const float* cb,
                                              int k, float zn, const float* en_s) {
    const ulonglong2* cp = (const ulonglong2*)(cb + (size_t)k * C_);
    unsigned long long a0 = 0ull, a1 = 0ull, a2 = 0ull, a3 = 0ull;
    #pragma unroll
    for (int j = 0; j < 16; j += 2) {
        ulonglong2 v0 = cp[j];
        ulonglong2 v1 = cp[j + 1];
        a0 = fma2(pack2(zs[4 * j + 0], zs[4 * j + 1]), v0.x, a0);
        a1 = fma2(pack2(zs[4 * j + 2], zs[4 * j + 3]), v0.y, a1);
        a2 = fma2(pack2(zs[4 * j + 4], zs[4 * j + 5]), v1.x, a2);
        a3 = fma2(pack2(zs[4 * j + 6], zs[4 * j + 7]), v1.y, a3);
    }
    a0 = add2(a0, a1); a2 = add2(a2, a3); a0 = add2(a0, a2);
    float2 f = unpack2(a0);
    return (zn + en_s[k]) - 2.0f * (f.x + f.y);
}

// ---------------- kernel ----------------
__global__ void __launch_bounds__(TPB, 1)
vq_mma(const float* __restrict__ z, const float* __restrict__ cb,
       float* __restrict__ zq_out, float* __restrict__ idx_out,
       float* __restrict__ loss_out) {
    extern __shared__ char smem[];
    uint32_t* e0p = (uint32_t*)(smem + SM_E0);
    uint32_t* e1p = (uint32_t*)(smem + SM_E1);
    float* zsm  = (float*)(smem + SM_Z);
    float* en_s = (float*)(smem + SM_EN);
    float* sm1  = (float*)(smem + SM_M1);
    int*   sk1  = (int*)  (smem + SM_K1);
    float* sm2  = (float*)(smem + SM_M2);
    int*   sk2  = (int*)  (smem + SM_K2);
    float* sm3  = (float*)(smem + SM_M3);
    int*   flst = (int*)  (smem + SM_FL);
    int*   fcnt = (int*)  (smem + SM_FC);
    float* red  = (float*)(smem + SM_RED);

    const int tid  = threadIdx.x;
    const int wid  = tid >> 5;
    const int lane = tid & 31;
    const int q    = lane & 3;
    const int g    = lane >> 2;

    // --- stage codebook ONCE: bf16 2-splits in fragment-permuted layout ---
    // word w (bf16 pair 2w,2w+1) of row n -> slot q*8 + ks*2 + half, q=(w&7)&3, half=(w&7)>>2, ks=w>>3
    {
        const float2* cb2 = (const float2*)cb;
        for (int i = tid; i < K_ * 32; i += TPB) {
            const int n = i >> 5, w = i & 31;
            float2 v = cb2[i];
            uint32_t mn, rs;
            bfsplit2(v.x, v.y, mn, rs);
            const int rem = w & 7;
            const int nw = (rem & 3) * 8 + (w >> 3) * 2 + (rem >> 2);
            e0p[n * EW + nw] = mn;
            e1p[n * EW + nw] = rs;
        }
    }
    for (int k = tid; k < K_; k += TPB) {
        const float* cp = cb + k * C_;
        float s = 0.f;
        #pragma unroll
        for (int c = 0; c < C_; ++c) s = fmaf(cp[c], cp[c], s);
        en_s[k] = s;
    }

    float lsum = 0.f;

    // --- persistent tile loop ---
    for (int tile = blockIdx.x; tile < NTILES; tile += GRID_) {
        __syncthreads();                       // prev tile consumers done
        if (tid == 0) *fcnt = 0;

        const int bb  = tile >> 4;
        const int hwb = (tile & 15) * TILE_M;
        const float* zb = z + (size_t)bb * (C_ * HW_);

        // stage z tile (256 pixels, transposed to [pixel][channel])
        for (int i = tid; i < 64 * 64; i += TPB) {
            const int c = i >> 6, j = i & 63;
            float4 v = *(const float4*)(zb + c * HW_ + hwb + j * 4);
            zsm[(j * 4 + 0) * ZPAD + c] = v.x;
            zsm[(j * 4 + 1) * ZPAD + c] = v.y;
            zsm[(j * 4 + 2) * ZPAD + c] = v.z;
            zsm[(j * 4 + 3) * ZPAD + c] = v.w;
        }
        __syncthreads();

        // build A fragments (2 rowfrags x 4 ksteps), rows wid*32 + rf*16 + {g, g+8}
        uint32_t az0[2][4][4], az1[2][4][4];
        #pragma unroll
        for (int rf = 0; rf < 2; ++rf) {
            const int r0 = wid * 32 + rf * 16 + g;
            const int r1 = r0 + 8;
            #pragma unroll
            for (int ks = 0; ks < 4; ++ks) {
                const int kc = ks * 16 + 2 * q;
                bfsplit2(zsm[r0 * ZPAD + kc],     zsm[r0 * ZPAD + kc + 1], az0[rf][ks][0], az1[rf][ks][0]);
                bfsplit2(zsm[r1 * ZPAD + kc],     zsm[r1 * ZPAD + kc + 1], az0[rf][ks][1], az1[rf][ks][1]);
                bfsplit2(zsm[r0 * ZPAD + kc + 8], zsm[r0 * ZPAD + kc + 9], az0[rf][ks][2], az1[rf][ks][2]);
                bfsplit2(zsm[r1 * ZPAD + kc + 8], zsm[r1 * ZPAD + kc + 9], az0[rf][ks][3], az1[rf][ks][3]);
            }
        }

        // screen: top-3 tracking; tracker t = rf*2+pr -> row wid*32 + rf*16 + pr*8 + g
        float m1v[4], m2v[4], m3v[4];
        int   k1v[4], k2v[4];
        #pragma unroll
        for (int t = 0; t < 4; ++t) {
            m1v[t] = 3.4e38f; m2v[t] = 3.4e38f; m3v[t] = 3.4e38f;
            k1v[t] = 0; k2v[t] = 0;
        }

        #pragma unroll 1
        for (int nt = 0; nt < 64; ++nt) {
            const int n = nt * 8 + g;
            const uint4* p0 = (const uint4*)(e0p + n * EW + q * 8);
            const uint4* p1 = (const uint4*)(e1p + n * EW + q * 8);
            uint4 b0a = p0[0], b0b = p0[1];   // e0: ks0/ks1, ks2/ks3
            uint4 b1a = p1[0], b1b = p1[1];   // e1

            float t00[2][4] = {{0.f,0.f,0.f,0.f},{0.f,0.f,0.f,0.f}};
            float t10[2][4] = {{0.f,0.f,0.f,0.f},{0.f,0.f,0.f,0.f}};
            float t01[2][4] = {{0.f,0.f,0.f,0.f},{0.f,0.f,0.f,0.f}};
            #pragma unroll
            for (int rf = 0; rf < 2; ++rf) {
                mma16816(t00[rf], az0[rf][0], b0a.x, b0a.y);
                mma16816(t10[rf], az1[rf][0], b0a.x, b0a.y);
                mma16816(t01[rf], az0[rf][0], b1a.x, b1a.y);
                mma16816(t00[rf], az0[rf][1], b0a.z, b0a.w);
                mma16816(t10[rf], az1[rf][1], b0a.z, b0a.w);
                mma16816(t01[rf], az0[rf][1], b1a.z, b1a.w);
                mma16816(t00[rf], az0[rf][2], b0b.x, b0b.y);
                mma16816(t10[rf], az1[rf][2], b0b.x, b0b.y);
                mma16816(t01[rf], az0[rf][2], b1b.x, b1b.y);
                mma16816(t00[rf], az0[rf][3], b0b.z, b0b.w);
                mma16816(t10[rf], az1[rf][3], b0b.z, b0b.w);
                mma16816(t01[rf], az0[rf][3], b1b.z, b1b.w);
            }

            const int kc0 = nt * 8 + 2 * q;
            const float en0 = en_s[kc0], en1 = en_s[kc0 + 1];
            #pragma unroll
            for (int rf = 0; rf < 2; ++rf) {
                #pragma unroll
                for (int pr = 0; pr < 2; ++pr) {
                    const int t = rf * 2 + pr;
                    float d0 = t00[rf][pr * 2 + 0] + t10[rf][pr * 2 + 0] + t01[rf][pr * 2 + 0];
                    float d1 = t00[rf][pr * 2 + 1] + t10[rf][pr * 2 + 1] + t01[rf][pr * 2 + 1];
                    float s0 = fmaf(-2.f, d0, en0);
                    float s1 = fmaf(-2.f, d1, en1);
                    if (s0 < m1v[t])      { m3v[t]=m2v[t]; m2v[t]=m1v[t]; k2v[t]=k1v[t]; m1v[t]=s0; k1v[t]=kc0; }
                    else if (s0 < m2v[t]) { m3v[t]=m2v[t]; m2v[t]=s0; k2v[t]=kc0; }
                    else if (s0 < m3v[t]) { m3v[t]=s0; }
                    if (s1 < m1v[t])      { m3v[t]=m2v[t]; m2v[t]=m1v[t]; k2v[t]=k1v[t]; m1v[t]=s1; k1v[t]=kc0+1; }
                    else if (s1 < m2v[t]) { m3v[t]=m2v[t]; m2v[t]=s1; k2v[t]=kc0+1; }
                    else if (s1 < m3v[t]) { m3v[t]=s1; }
                }
            }
        }

        // reduce top-3 across the 4 q-lanes of each row; lex (value, index) order
        #pragma unroll
        for (int t = 0; t < 4; ++t) {
            float m1 = m1v[t], m2 = m2v[t], m3 = m3v[t];
            int   k1 = k1v[t], k2 = k2v[t];
            #pragma unroll
            for (int off = 1; off <= 2; off <<= 1) {
                float bm1 = __shfl_xor_sync(0xFFFFFFFFu, m1, off);
                float bm2 = __shfl_xor_sync(0xFFFFFFFFu, m2, off);
                float bm3 = __shfl_xor_sync(0xFFFFFFFFu, m3, off);
                int   bk1 = __shfl_xor_sync(0xFFFFFFFFu, k1, off);
                int   bk2 = __shfl_xor_sync(0xFFFFFFFFu, k2, off);
                float nm1, nm2, nm3; int nk1, nk2;
                bool bfirst = (bm1 < m1) || (bm1 == m1 && bk1 < k1);
                if (!bfirst) {
                    nm1 = m1; nk1 = k1;
                    bool bnext = (bm1 < m2) || (bm1 == m2 && bk1 < k2);
                    if (!bnext) { nm2 = m2;  nk2 = k2;  nm3 = fminf(m3, bm1); }
                    else        { nm2 = bm1; nk2 = bk1; nm3 = fminf(m2, bm2); }
                } else {
                    nm1 = bm1; nk1 = bk1;
                    bool anext = (m1 < bm2) || (m1 == bm2 && k1 < bk2);
                    if (anext)  { nm2 = m1;  nk2 = k1;  nm3 = fminf(m2, bm2); }
                    else        { nm2 = bm2; nk2 = bk2; nm3 = fminf(m1, bm3); }
                }
                m1 = nm1; m2 = nm2; m3 = nm3; k1 = nk1; k2 = nk2;
            }
            if (q == 0) {
                const int row = wid * 32 + (t >> 1) * 16 + (t & 1) * 8 + g;
                sm1[row] = m1; sk1[row] = k1;
                sm2[row] = m2; sk2[row] = k2;
                sm3[row] = m3;
            }
        }
        __syncthreads();

        // decision pass: one thread per pixel
        {
            const int m = tid;
            const float m1 = sm1[m], m2 = sm2[m], m3 = sm3[m];
            const int k1 = sk1[m], k2 = sk2[m];
            const float* zs = zsm + m * ZPAD;
            int kk = -1;
            if (m2 - m1 >= EPS_SCREEN) {
                kk = k1;
            } else if (m3 - m1 >= EPS_SCREEN) {
                // exact 2-candidate compare (round-1 arithmetic)
                float zn = 0.f;
                #pragma unroll
                for (int i = 0; i < 32; ++i) {
                    float x = zs[2 * i], y = zs[2 * i + 1];
                    zn = fmaf(x, x, zn); zn = fmaf(y, y, zn);
                }
                float dA = exact_dist_k(zs, cb, k1, zn, en_s);
                float dB = exact_dist_k(zs, cb, k2, zn, en_s);
                kk = (dB < dA || (dB == dA && k2 < k1)) ? k2 : k1;
            } else {
                flst[atomicAdd(fcnt, 1)] = m;
            }
            if (kk >= 0) {
                const int p  = tile * TILE_M + m;
                const int hw = hwb + m;
                const float4* cr = (const float4*)(cb + kk * C_);
                float* zo = zq_out + (size_t)bb * (C_ * HW_) + hw;
                float ls = 0.f;
                #pragma unroll
                for (int j4 = 0; j4 < 16; ++j4) {
                    float4 qv = cr[j4];
                    const float qa[4] = {qv.x, qv.y, qv.z, qv.w};
                    #pragma unroll
                    for (int t = 0; t < 4; ++t) {
                        const int c = j4 * 4 + t;
                        float x = zs[c];
                        float d = qa[t] - x;
                        ls = fmaf(d, d, ls);
                        zo[c * HW_] = x + d;
                    }
                }
                lsum += ls;
                idx_out[p] = (float)kk;
            }
        }
        __syncthreads();

        // rare full exact fallback: one warp per flagged pixel
        const int F = *fcnt;
        for (int e = wid; e < F; e += 8) {
            const int mm = flst[e];
            const float* zs = zsm + mm * ZPAD;
            float zn = 0.f;
            unsigned long long zr[32];
            #pragma unroll
            for (int i = 0; i < 32; ++i) {
                float x = zs[2 * i], y = zs[2 * i + 1];
                zn = fmaf(x, x, zn); zn = fmaf(y, y, zn);
                zr[i] = pack2(x, y);
            }
            float best = 3.402823466e38f;
            int   bk   = 0;
            #pragma unroll 1
            for (int t = 0; t < 16; ++t) {
                const int k = lane + (t << 5);
                const ulonglong2* cp = (const ulonglong2*)(cb + (size_t)k * C_);
                unsigned long long a0 = 0ull, a1 = 0ull, a2 = 0ull, a3 = 0ull;
                #pragma unroll
                for (int j = 0; j < 16; j += 2) {
                    ulonglong2 v0 = cp[j];
                    ulonglong2 v1 = cp[j + 1];
                    a0 = fma2(zr[2 * j + 0], v0.x, a0);
                    a1 = fma2(zr[2 * j + 1], v0.y, a1);
                    a2 = fma2(zr[2 * j + 2], v1.x, a2);
                    a3 = fma2(zr[2 * j + 3], v1.y, a3);
                }
                a0 = add2(a0, a1); a2 = add2(a2, a3); a0 = add2(a0, a2);
                float2 f = unpack2(a0);
                float dist = (zn + en_s[k]) - 2.0f * (f.x + f.y);
                if (dist < best) { best = dist; bk = k; }
            }
            #pragma unroll
            for (int off = 16; off > 0; off >>= 1) {
                float ob = __shfl_down_sync(0xFFFFFFFFu, best, off);
                int   ok = __shfl_down_sync(0xFFFFFFFFu, bk, off);
                if (ob < best || (ob == best && ok < bk)) { best = ob; bk = ok; }
            }
            if (lane == 0) {
                const int p  = tile * TILE_M + mm;
                const int hw = hwb + mm;
                const float* cbv = cb + bk * C_;
                float* zo = zq_out + (size_t)bb * (C_ * HW_) + hw;
                float ls = 0.f;
                #pragma unroll
                for (int c = 0; c < C_; ++c) {
                    float x = zs[c];
                    float d = cbv[c] - x;
                    ls = fmaf(d, d, ls);
                    zo[c * HW_] = x + d;
                }
                lsum += ls;
                idx_out[p] = (float)bk;
            }
        }
    }

    // --- loss reduction ---
    __syncthreads();
    #pragma unroll
    for (int off = 16; off > 0; off >>= 1)
        lsum += __shfl_down_sync(0xFFFFFFFFu, lsum, off);
    if (lane == 0) red[wid] = lsum;
    __syncthreads();
    if (tid == 0) {
        float t = 0.f;
        #pragma unroll
        for (int w = 0; w < 8; ++w) t += red[w];
        g_partials[blockIdx.x] = t;
        __threadfence();
        unsigned int old = atomicAdd(&g_count, 1u);
        *fcnt = (old == GRID_ - 1) ? 1 : 0;
    }
    __syncthreads();
    if (*fcnt) {
        float v = 0.f;
        if (tid < GRID_)
            asm volatile("ld.global.cg.f32 %0, [%1];" : "=f"(v) : "l"(g_partials + tid));
        red[tid] = v;
        __syncthreads();
        for (int off = 128; off > 0; off >>= 1) {
            if (tid < off) red[tid] += red[tid + off];
            __syncthreads();
        }
        if (tid == 0) {
            float qv = red[0] / (float)NE;   // q_loss == e_loss numerically
            loss_out[0] = qv + 0.25f * qv;
            g_count = 0;                     // reset for next graph replay
        }
    }
}

extern "C" void kernel_launch(void* const* d_in, const int* in_sizes, int n_in,
                              void* d_out, int out_size) {
    const float* z  = (const float*)d_in[0];   // z_e [32,64,64,64] f32
    const float* cb = (const float*)d_in[1];   // codebook [512,64] f32
    float* out  = (float*)d_out;
    float* zq   = out;               // [NE]
    float* idx  = out + NE;          // [NPIX]
    float* loss = out + NE + NPIX;   // [1]

    cudaFuncSetAttribute(vq_mma, cudaFuncAttributeMaxDynamicSharedMemorySize, SM_TOTAL);
    vq_mma<<<GRID_, TPB, SM_TOTAL>>>(z, cb, zq, idx, loss);
}

// round 9
// speedup vs baseline: 1.5925x; 1.1087x over previous
#include <cuda_runtime.h>
#include <cuda_bf16.h>
#include <cstdint>

// ---------------- problem shape ----------------
#define B_    32
#define C_    64
#define HW_   4096
#define K_    512
#define NPIX  131072
#define NE    8388608
#define TPB   512
#define NWARP 16
#define TILE_M 256
#define NTILES (NPIX / TILE_M)   // 512
#define GRID_ 148
#define EPS_SCREEN 1e-4f
#define EW    36                 // permuted codebook row stride in u32 words
#define ZPAD  65                 // z tile row stride in f32

// ---------------- smem layout (bytes) ----------------
#define SM_E0   0                        // 512 x 36 u32 = 73728
#define SM_E1   73728                    // 73728
#define SM_Z    147456                   // 256 x 65 f32 = 66560
#define SM_EN   214016                   // 512 f32 = 2048
#define SM_M1   216064                   // 256 f32
#define SM_K1   217088                   // 256 i32
#define SM_M2   218112                   // 256 f32
#define SM_K2   219136                   // 256 i32
#define SM_M3   220160                   // 256 f32
#define SM_FL   221184                   // 256 i32
#define SM_FC   222208                   // 8
#define SM_RED  222216                   // 256 f32
#define SM_TOTAL 223240

__device__ float g_partials[GRID_];
__device__ unsigned int g_count;

// ---------------- helpers ----------------
__device__ __forceinline__ void mma16816(float* c, const uint32_t* a,
                                         uint32_t b0, uint32_t b1) {
    asm volatile(
        "mma.sync.aligned.m16n8k16.row.col.f32.bf16.bf16.f32 "
        "{%0,%1,%2,%3}, {%4,%5,%6,%7}, {%8,%9}, {%0,%1,%2,%3};"
        : "+f"(c[0]), "+f"(c[1]), "+f"(c[2]), "+f"(c[3])
        : "r"(a[0]), "r"(a[1]), "r"(a[2]), "r"(a[3]), "r"(b0), "r"(b1));
}

__device__ __forceinline__ void bfsplit2(float x, float y,
                                         uint32_t& mn, uint32_t& rs) {
    __nv_bfloat16 hx = __float2bfloat16(x);
    __nv_bfloat16 hy = __float2bfloat16(y);
    float rx = x - __bfloat162float(hx);
    float ry = y - __bfloat162float(hy);
    __nv_bfloat162 m; m.x = hx; m.y = hy;
    __nv_bfloat162 r; r.x = __float2bfloat16(rx); r.y = __float2bfloat16(ry);
    mn = *(uint32_t*)&m;
    rs = *(uint32_t*)&r;
}

// packed f32x2 (exact-path arithmetic, identical to rounds 1..8)
__device__ __forceinline__ unsigned long long fma2(unsigned long long a,
                                                   unsigned long long b,
                                                   unsigned long long c) {
    unsigned long long d;
    asm("fma.rn.f32x2 %0, %1, %2, %3;" : "=l"(d) : "l"(a), "l"(b), "l"(c));
    return d;
}
__device__ __forceinline__ unsigned long long add2(unsigned long long a,
                                                   unsigned long long b) {
    unsigned long long d;
    asm("add.rn.f32x2 %0, %1, %2;" : "=l"(d) : "l"(a), "l"(b));
    return d;
}
__device__ __forceinline__ unsigned long long pack2(float x, float y) {
    unsigned long long u;
    asm("mov.b64 %0, {%1, %2};" : "=l"(u) : "f"(x), "f"(y));
    return u;
}
__device__ __forceinline__ float2 unpack2(unsigned long long u) {
    float2 f;
    asm("mov.b64 {%0, %1}, %2;" : "=f"(f.x), "=f"(f.y) : "l"(u));
    return f;
}

// exact dist for one code, bit-identical to round-1 chain (zs = 64 f32 in smem)
__device__ __forceinline__ float exact_dist_k(const float* zs, const float* cb,
                                              int k, float zn, const float* en_s) {
    const ulonglong2* cp = (const ulonglong2*)(cb + (size_t)k * C_);
    unsigned long long a0 = 0ull, a1 = 0ull, a2 = 0ull, a3 = 0ull;
    #pragma unroll
    for (int j = 0; j < 16; j += 2) {
        ulonglong2 v0 = cp[j];
        ulonglong2 v1 = cp[j + 1];
        a0 = fma2(pack2(zs[4 * j + 0], zs[4 * j + 1]), v0.x, a0);
        a1 = fma2(pack2(zs[4 * j + 2], zs[4 * j + 3]), v0.y, a1);
        a2 = fma2(pack2(zs[4 * j + 4], zs[4 * j + 5]), v1.x, a2);
        a3 = fma2(pack2(zs[4 * j + 6], zs[4 * j + 7]), v1.y, a3);
    }
    a0 = add2(a0, a1); a2 = add2(a2, a3); a0 = add2(a0, a2);
    float2 f = unpack2(a0);
    return (zn + en_s[k]) - 2.0f * (f.x + f.y);
}

// ---------------- kernel ----------------
__global__ void __launch_bounds__(TPB, 1)
vq_mma(const float* __restrict__ z, const float* __restrict__ cb,
       float* __restrict__ zq_out, float* __restrict__ idx_out,
       float* __restrict__ loss_out) {
    extern __shared__ char smem[];
    uint32_t* e0p = (uint32_t*)(smem + SM_E0);
    uint32_t* e1p = (uint32_t*)(smem + SM_E1);
    float* zsm  = (float*)(smem + SM_Z);
    float* en_s = (float*)(smem + SM_EN);
    float* sm1  = (float*)(smem + SM_M1);
    int*   sk1  = (int*)  (smem + SM_K1);
    float* sm2  = (float*)(smem + SM_M2);
    int*   sk2  = (int*)  (smem + SM_K2);
    float* sm3  = (float*)(smem + SM_M3);
    int*   flst = (int*)  (smem + SM_FL);
    int*   fcnt = (int*)  (smem + SM_FC);
    float* red  = (float*)(smem + SM_RED);

    const int tid  = threadIdx.x;
    const int wid  = tid >> 5;
    const int lane = tid & 31;
    const int q    = lane & 3;
    const int g    = lane >> 2;

    // --- stage codebook ONCE: bf16 2-splits in fragment-permuted layout ---
    {
        const float2* cb2 = (const float2*)cb;
        for (int i = tid; i < K_ * 32; i += TPB) {
            const int n = i >> 5, w = i & 31;
            float2 v = cb2[i];
            uint32_t mn, rs;
            bfsplit2(v.x, v.y, mn, rs);
            const int rem = w & 7;
            const int nw = (rem & 3) * 8 + (w >> 3) * 2 + (rem >> 2);
            e0p[n * EW + nw] = mn;
            e1p[n * EW + nw] = rs;
        }
    }
    for (int k = tid; k < K_; k += TPB) {
        const float* cp = cb + k * C_;
        float s = 0.f;
        #pragma unroll
        for (int c = 0; c < C_; ++c) s = fmaf(cp[c], cp[c], s);
        en_s[k] = s;
    }

    float lsum = 0.f;

    // --- persistent tile loop ---
    for (int tile = blockIdx.x; tile < NTILES; tile += GRID_) {
        __syncthreads();
        if (tid == 0) *fcnt = 0;

        const int bb  = tile >> 4;
        const int hwb = (tile & 15) * TILE_M;
        const float* zb = z + (size_t)bb * (C_ * HW_);

        // stage z tile (256 pixels, transposed to [pixel][channel])
        for (int i = tid; i < 64 * 64; i += TPB) {
            const int c = i >> 6, j = i & 63;
            float4 v = *(const float4*)(zb + c * HW_ + hwb + j * 4);
            zsm[(j * 4 + 0) * ZPAD + c] = v.x;
            zsm[(j * 4 + 1) * ZPAD + c] = v.y;
            zsm[(j * 4 + 2) * ZPAD + c] = v.z;
            zsm[(j * 4 + 3) * ZPAD + c] = v.w;
        }
        __syncthreads();

        // build A fragments: ONE rowfrag per warp, rows wid*16 + {g, g+8}
        uint32_t az0[4][4], az1[4][4];
        {
            const int r0 = wid * 16 + g;
            const int r1 = r0 + 8;
            #pragma unroll
            for (int ks = 0; ks < 4; ++ks) {
                const int kc = ks * 16 + 2 * q;
                bfsplit2(zsm[r0 * ZPAD + kc],     zsm[r0 * ZPAD + kc + 1], az0[ks][0], az1[ks][0]);
                bfsplit2(zsm[r1 * ZPAD + kc],     zsm[r1 * ZPAD + kc + 1], az0[ks][1], az1[ks][1]);
                bfsplit2(zsm[r0 * ZPAD + kc + 8], zsm[r0 * ZPAD + kc + 9], az0[ks][2], az1[ks][2]);
                bfsplit2(zsm[r1 * ZPAD + kc + 8], zsm[r1 * ZPAD + kc + 9], az0[ks][3], az1[ks][3]);
            }
        }

        // screen: top-3 per tracker; tracker pr -> row wid*16 + pr*8 + g
        float m1v[2] = {3.4e38f, 3.4e38f};
        float m2v[2] = {3.4e38f, 3.4e38f};
        float m3v[2] = {3.4e38f, 3.4e38f};
        int   k1v[2] = {0, 0};
        int   k2v[2] = {0, 0};

        #pragma unroll 1
        for (int nt = 0; nt < 64; ++nt) {
            const int n = nt * 8 + g;
            const uint4* p0 = (const uint4*)(e0p + n * EW + q * 8);
            const uint4* p1 = (const uint4*)(e1p + n * EW + q * 8);
            uint4 b0a = p0[0], b0b = p0[1];
            uint4 b1a = p1[0], b1b = p1[1];

            float t00[4] = {0.f, 0.f, 0.f, 0.f};
            float t10[4] = {0.f, 0.f, 0.f, 0.f};
            float t01[4] = {0.f, 0.f, 0.f, 0.f};
            mma16816(t00, az0[0], b0a.x, b0a.y);
            mma16816(t10, az1[0], b0a.x, b0a.y);
            mma16816(t01, az0[0], b1a.x, b1a.y);
            mma16816(t00, az0[1], b0a.z, b0a.w);
            mma16816(t10, az1[1], b0a.z, b0a.w);
            mma16816(t01, az0[1], b1a.z, b1a.w);
            mma16816(t00, az0[2], b0b.x, b0b.y);
            mma16816(t10, az1[2], b0b.x, b0b.y);
            mma16816(t01, az0[2], b1b.x, b1b.y);
            mma16816(t00, az0[3], b0b.z, b0b.w);
            mma16816(t10, az1[3], b0b.z, b0b.w);
            mma16816(t01, az0[3], b1b.z, b1b.w);

            const int kc0 = nt * 8 + 2 * q;
            const float en0 = en_s[kc0], en1 = en_s[kc0 + 1];
            #pragma unroll
            for (int pr = 0; pr < 2; ++pr) {
                float d0 = t00[pr * 2 + 0] + t10[pr * 2 + 0] + t01[pr * 2 + 0];
                float d1 = t00[pr * 2 + 1] + t10[pr * 2 + 1] + t01[pr * 2 + 1];
                float s0 = fmaf(-2.f, d0, en0);
                float s1 = fmaf(-2.f, d1, en1);
                if (s0 < m1v[pr])      { m3v[pr]=m2v[pr]; m2v[pr]=m1v[pr]; k2v[pr]=k1v[pr]; m1v[pr]=s0; k1v[pr]=kc0; }
                else if (s0 < m2v[pr]) { m3v[pr]=m2v[pr]; m2v[pr]=s0; k2v[pr]=kc0; }
                else if (s0 < m3v[pr]) { m3v[pr]=s0; }
                if (s1 < m1v[pr])      { m3v[pr]=m2v[pr]; m2v[pr]=m1v[pr]; k2v[pr]=k1v[pr]; m1v[pr]=s1; k1v[pr]=kc0+1; }
                else if (s1 < m2v[pr]) { m3v[pr]=m2v[pr]; m2v[pr]=s1; k2v[pr]=kc0+1; }
                else if (s1 < m3v[pr]) { m3v[pr]=s1; }
            }
        }

        // reduce top-3 across the 4 q-lanes of each row
        #pragma unroll
        for (int t = 0; t < 2; ++t) {
            float m1 = m1v[t], m2 = m2v[t], m3 = m3v[t];
            int   k1 = k1v[t], k2 = k2v[t];
            #pragma unroll
            for (int off = 1; off <= 2; off <<= 1) {
                float bm1 = __shfl_xor_sync(0xFFFFFFFFu, m1, off);
                float bm2 = __shfl_xor_sync(0xFFFFFFFFu, m2, off);
                float bm3 = __shfl_xor_sync(0xFFFFFFFFu, m3, off);
                int   bk1 = __shfl_xor_sync(0xFFFFFFFFu, k1, off);
                int   bk2 = __shfl_xor_sync(0xFFFFFFFFu, k2, off);
                float nm1, nm2, nm3; int nk1, nk2;
                bool bfirst = (bm1 < m1) || (bm1 == m1 && bk1 < k1);
                if (!bfirst) {
                    nm1 = m1; nk1 = k1;
                    bool bnext = (bm1 < m2) || (bm1 == m2 && bk1 < k2);
                    if (!bnext) { nm2 = m2;  nk2 = k2;  nm3 = fminf(m3, bm1); }
                    else        { nm2 = bm1; nk2 = bk1; nm3 = fminf(m2, bm2); }
                } else {
                    nm1 = bm1; nk1 = bk1;
                    bool anext = (m1 < bm2) || (m1 == bm2 && k1 < bk2);
                    if (anext)  { nm2 = m1;  nk2 = k1;  nm3 = fminf(m2, bm2); }
                    else        { nm2 = bm2; nk2 = bk2; nm3 = fminf(m1, bm3); }
                }
                m1 = nm1; m2 = nm2; m3 = nm3; k1 = nk1; k2 = nk2;
            }
            if (q == 0) {
                const int row = wid * 16 + t * 8 + g;
                sm1[row] = m1; sk1[row] = k1;
                sm2[row] = m2; sk2[row] = k2;
                sm3[row] = m3;
            }
        }
        __syncthreads();

        // decision pass: first 256 threads, one per pixel
        if (tid < TILE_M) {
            const int m = tid;
            const float m1 = sm1[m], m2 = sm2[m], m3 = sm3[m];
            const int k1 = sk1[m], k2 = sk2[m];
            const float* zs = zsm + m * ZPAD;
            int kk = -1;
            if (m2 - m1 >= EPS_SCREEN) {
                kk = k1;
            } else if (m3 - m1 >= EPS_SCREEN) {
                float zn = 0.f;
                #pragma unroll
                for (int i = 0; i < 32; ++i) {
                    float x = zs[2 * i], y = zs[2 * i + 1];
                    zn = fmaf(x, x, zn); zn = fmaf(y, y, zn);
                }
                float dA = exact_dist_k(zs, cb, k1, zn, en_s);
                float dB = exact_dist_k(zs, cb, k2, zn, en_s);
                kk = (dB < dA || (dB == dA && k2 < k1)) ? k2 : k1;
            } else {
                flst[atomicAdd(fcnt, 1)] = m;
            }
            if (kk >= 0) {
                const int p  = tile * TILE_M + m;
                const int hw = hwb + m;
                const float4* cr = (const float4*)(cb + kk * C_);
                float* zo = zq_out + (size_t)bb * (C_ * HW_) + hw;
                float ls = 0.f;
                #pragma unroll
                for (int j4 = 0; j4 < 16; ++j4) {
                    float4 qv = cr[j4];
                    const float qa[4] = {qv.x, qv.y, qv.z, qv.w};
                    #pragma unroll
                    for (int t = 0; t < 4; ++t) {
                        const int c = j4 * 4 + t;
                        float x = zs[c];
                        float d = qa[t] - x;
                        ls = fmaf(d, d, ls);
                        zo[c * HW_] = x + d;
                    }
                }
                lsum += ls;
                idx_out[p] = (float)kk;
            }
        }
        __syncthreads();

        // rare full exact fallback: one warp per flagged pixel, lanes strided over codes
        const int F = *fcnt;
        for (int e = wid; e < F; e += NWARP) {
            const int mm = flst[e];
            const float* zs = zsm + mm * ZPAD;
            float zn = 0.f;
            #pragma unroll
            for (int i = 0; i < 32; ++i) {
                float x = zs[2 * i], y = zs[2 * i + 1];
                zn = fmaf(x, x, zn); zn = fmaf(y, y, zn);
            }
            float best = 3.402823466e38f;
            int   bk   = 0;
            #pragma unroll 1
            for (int t = 0; t < 16; ++t) {
                const int k = lane + (t << 5);
                float dist = exact_dist_k(zs, cb, k, zn, en_s);
                if (dist < best) { best = dist; bk = k; }
            }
            #pragma unroll
            for (int off = 16; off > 0; off >>= 1) {
                float ob = __shfl_down_sync(0xFFFFFFFFu, best, off);
                int   ok = __shfl_down_sync(0xFFFFFFFFu, bk, off);
                if (ob < best || (ob == best && ok < bk)) { best = ob; bk = ok; }
            }
            if (lane == 0) {
                const int p  = tile * TILE_M + mm;
                const int hw = hwb + mm;
                const float* cbv = cb + bk * C_;
                float* zo = zq_out + (size_t)bb * (C_ * HW_) + hw;
                float ls = 0.f;
                #pragma unroll
                for (int c = 0; c < C_; ++c) {
                    float x = zs[c];
                    float d = cbv[c] - x;
                    ls = fmaf(d, d, ls);
                    zo[c * HW_] = x + d;
                }
                lsum += ls;
                idx_out[p] = (float)bk;
            }
        }
    }

    // --- loss reduction ---
    __syncthreads();
    #pragma unroll
    for (int off = 16; off > 0; off >>= 1)
        lsum += __shfl_down_sync(0xFFFFFFFFu, lsum, off);
    if (lane == 0) red[wid] = lsum;
    __syncthreads();
    if (tid == 0) {
        float t = 0.f;
        #pragma unroll
        for (int w = 0; w < NWARP; ++w) t += red[w];
        g_partials[blockIdx.x] = t;
        __threadfence();
        unsigned int old = atomicAdd(&g_count, 1u);
        *fcnt = (old == GRID_ - 1) ? 1 : 0;
    }
    __syncthreads();
    if (*fcnt) {
        if (tid < 256) {
            float v = 0.f;
            if (tid < GRID_)
                asm volatile("ld.global.cg.f32 %0, [%1];" : "=f"(v) : "l"(g_partials + tid));
            red[tid] = v;
        }
        __syncthreads();
        for (int off = 128; off > 0; off >>= 1) {
            if (tid < off) red[tid] += red[tid + off];
            __syncthreads();
        }
        if (tid == 0) {
            float qv = red[0] / (float)NE;   // q_loss == e_loss numerically
            loss_out[0] = qv + 0.25f * qv;
            g_count = 0;                     // reset for next graph replay
        }
    }
}

extern "C" void kernel_launch(void* const* d_in, const int* in_sizes, int n_in,
                              void* d_out, int out_size) {
    const float* z  = (const float*)d_in[0];   // z_e [32,64,64,64] f32
    const float* cb = (const float*)d_in[1];   // codebook [512,64] f32
    float* out  = (float*)d_out;
    float* zq   = out;               // [NE]
    float* idx  = out + NE;          // [NPIX]
    float* loss = out + NE + NPIX;   // [1]

    cudaFuncSetAttribute(vq_mma, cudaFuncAttributeMaxDynamicSharedMemorySize, SM_TOTAL);
    vq_mma<<<GRID_, TPB, SM_TOTAL>>>(z, cb, zq, idx, loss);
}